// round 2
// baseline (speedup 1.0000x reference)
#include <cuda_runtime.h>

#define MM 1000
#define BB 16
#define LL 499500            // MM*(MM-1)/2
#define NODES (BB * MM)
#define RT 64                // rows per tile

// Node-sized scratch state (allocation-free: __device__ globals)
__device__ float g_v[NODES];
__device__ float g_p2[NODES];
__device__ float g_dtp1[NODES];
__device__ float g_dtw0[NODES];
__device__ float g_dtw1[NODES];

__global__ void init_kernel(const float* gnp, const float* alphap) {
    int x = blockIdx.x * blockDim.x + threadIdx.x;
    if (x >= NODES) return;
    float gn = *gnp, alpha = *alphap;
    g_v[x] = 0.f;
    // p2_0 = prox(y2_0 = 0)
    float up = fmaxf(4.f * gn * alpha, 1e-8f);
    g_p2[x] = -0.5f * sqrtf(up);
    g_dtp1[x] = 0.f;
    g_dtw0[x] = 0.f;
    g_dtw1[x] = 0.f;
}

// After edge pass t: dtw_old holds DT(w_t), dtw_new holds DT(w_{t+1}), g_dtp1 holds DT(p1_t).
// v_{t+1} = p2_t + gn*(DT(p1_t) - DT(w_t));  p2_{t+1} = prox(v_{t+1} + gn*DT(w_{t+1}))
__global__ void node_kernel(const float* gnp, const float* alphap, int oldslot) {
    int x = blockIdx.x * blockDim.x + threadIdx.x;
    if (x >= NODES) return;
    float gn = *gnp, alpha = *alphap;
    float* dtw_old = oldslot ? g_dtw1 : g_dtw0;
    float* dtw_new = oldslot ? g_dtw0 : g_dtw1;
    float vn = g_p2[x] + gn * (g_dtp1[x] - dtw_old[x]);
    float y2 = vn + gn * dtw_new[x];
    float up = fmaxf(fmaf(y2, y2, 4.f * gn * alpha), 1e-8f);
    g_p2[x] = 0.5f * (y2 - sqrtf(up));
    g_v[x] = vn;
    g_dtp1[x] = 0.f;
    dtw_old[x] = 0.f;   // becomes accumulator for DT(w_{t+2})
}

// Tiled edge pass: thread = column j (256 cols per block), CTA = 64-row tile.
// Column-endpoint DT contributions accumulate in registers; row-endpoint via
// per-row warp butterfly reduce into smem. Global atomics only per-tile (~640/CTA).
__global__ __launch_bounds__(256) void edge_kernel(
    const float* __restrict__ z,
    const float* __restrict__ wprev_base,
    float* __restrict__ wout_base,
    const float* __restrict__ gnp,
    const float* __restrict__ betap,
    int first, int nxtslot, long long UL)
{
    // 40 non-empty tiles: J=0 -> I=0..3, J=1 -> I=0..7, J=2 -> I=0..11, J=3 -> I=0..15
    int tid = blockIdx.x;
    int b = blockIdx.y;
    int I, J;
    if (tid < 4)       { J = 0; I = tid; }
    else if (tid < 12) { J = 1; I = tid - 4; }
    else if (tid < 24) { J = 2; I = tid - 12; }
    else               { J = 3; I = tid - 24; }
    int i0 = I * RT;
    int j  = J * 256 + (int)threadIdx.x;

    float gn = *gnp, beta = *betap;
    float c1 = 1.f - 2.f * gn * beta;   // y1 = c1*w - gn*(v_i + v_j)
    float t2 = 2.f * gn;

    __shared__ float s_ngv[RT], s_ngp[RT], s_rp[RT], s_rw[RT];
    const float* vB = g_v  + b * MM;
    const float* pB = g_p2 + b * MM;
    for (int r = threadIdx.x; r < RT; r += 256) {
        int i = i0 + r;
        float vi = (i < MM) ? vB[i] : 0.f;
        float pi = (i < MM) ? pB[i] : 0.f;
        s_ngv[r] = -gn * vi;
        s_ngp[r] = -gn * pi;
        s_rp[r] = 0.f;
        s_rw[r] = 0.f;
    }
    __syncthreads();

    bool colv = (j < MM);
    float ngvj = colv ? -gn * vB[j] : 0.f;
    float ngpj = colv ? -gn * pB[j] : 0.f;
    float accP = 0.f, accW = 0.f;

    const float* zb = z + (size_t)b * LL;
    const float* wb = wprev_base + (size_t)b * UL;
    float*       ob = wout_base  + (size_t)b * UL;

    // row start in packed triu: rs(i) = i*(M-1) - i*(i-1)/2 ; e = rs(i) + j - i - 1
    int rsi = i0 * (MM - 1) - (i0 * (i0 - 1)) / 2;
    int lane = threadIdx.x & 31;

    for (int r = 0; r < RT; r++) {
        int i = i0 + r;
        if (i >= MM - 1) break;
        bool act = colv && (j > i);
        float p1 = 0.f, wn = 0.f;
        if (act) {
            int e = rsi + j - i - 1;
            float w  = first ? 0.f : wb[e];
            float zz = zb[e];
            float y1 = fmaf(c1, w, s_ngv[r] + ngvj);
            p1 = fmaxf(0.f, fmaf(-t2, zz, y1));
            float q1 = fmaf(c1, p1, s_ngp[r] + ngpj);
            wn = (w - y1) + q1;
            ob[e] = wn;
            accP += p1;   // DT(p1)[j]
            accW += wn;   // DT(w_new)[j]
        }
        if (__ballot_sync(0xFFFFFFFFu, act)) {
            float rp = p1, rw = wn;
            #pragma unroll
            for (int o = 16; o; o >>= 1) {
                rp += __shfl_xor_sync(0xFFFFFFFFu, rp, o);
                rw += __shfl_xor_sync(0xFFFFFFFFu, rw, o);
            }
            if (lane == 0) {
                atomicAdd(&s_rp[r], rp);
                atomicAdd(&s_rw[r], rw);
            }
        }
        rsi += (MM - 1) - i;
    }

    float* dtp1 = g_dtp1 + b * MM;
    float* dtw  = (nxtslot ? g_dtw1 : g_dtw0) + b * MM;
    if (colv && j > i0) {
        atomicAdd(&dtp1[j], accP);
        atomicAdd(&dtw[j],  accW);
    }
    __syncthreads();
    for (int r = threadIdx.x; r < RT; r += 256) {
        int i = i0 + r;
        if (i < MM - 1) {
            atomicAdd(&dtp1[i], s_rp[r]);
            atomicAdd(&dtw[i],  s_rw[r]);
        }
    }
}

extern "C" void kernel_launch(void* const* d_in, const int* in_sizes, int n_in,
                              void* d_out, int out_size) {
    const float* z     = (const float*)d_in[0];
    const float* gn    = (const float*)d_in[1];
    const float* alpha = (const float*)d_in[2];
    const float* beta  = (const float*)d_in[3];
    // d_in[4] = num_unroll (device int); derive U from out_size instead (host-visible)
    float* out = (float*)d_out;
    int U = out_size / (BB * LL);
    if (U <= 0) U = 15;
    long long UL = (long long)U * LL;

    init_kernel<<<(NODES + 255) / 256, 256>>>(gn, alpha);

    int cur = 0;   // slot holding DT(w_t); initially DT(w_0)=0
    for (int t = 0; t < U; t++) {
        int nxt = cur ^ 1;
        const float* wprev = (t == 0) ? out : (out + (size_t)(t - 1) * LL);
        float*       wout  = out + (size_t)t * LL;
        edge_kernel<<<dim3(40, BB), 256>>>(z, wprev, wout, gn, beta,
                                           (t == 0) ? 1 : 0, nxt, UL);
        if (t + 1 < U)
            node_kernel<<<(NODES + 255) / 256, 256>>>(gn, alpha, cur);
        cur = nxt;
    }
}

// round 5
// speedup vs baseline: 1.7112x; 1.7112x over previous
#include <cuda_runtime.h>

#define MM 1000
#define BB 16
#define LL 499500            // MM*(MM-1)/2
#define NODES (BB * MM)
#define RT 64                // rows per CTA tile
#define CH 8                 // rows per smem chunk
#define NCH (RT / CH)        // 8 chunks

// Node-sized scratch state (allocation-free: __device__ globals)
__device__ float g_v[NODES];
__device__ float g_p2[NODES];
__device__ float g_dtp1[NODES];
__device__ float g_dtw0[NODES];
__device__ float g_dtw1[NODES];

__global__ void init_kernel(const float* gnp, const float* alphap) {
    int x = blockIdx.x * blockDim.x + threadIdx.x;
    if (x >= NODES) return;
    float gn = *gnp, alpha = *alphap;
    g_v[x] = 0.f;
    float up = fmaxf(4.f * gn * alpha, 1e-8f);
    g_p2[x] = -0.5f * sqrtf(up);   // p2_0 = prox(0)
    g_dtp1[x] = 0.f;
    g_dtw0[x] = 0.f;
    g_dtw1[x] = 0.f;
}

// After edge pass t: dtw_old holds DT(w_t), dtw_new holds DT(w_{t+1}), g_dtp1 holds DT(p1_t).
// v_{t+1} = p2_t + gn*(DT(p1_t) - DT(w_t));  p2_{t+1} = prox(v_{t+1} + gn*DT(w_{t+1}))
__global__ void node_kernel(const float* gnp, const float* alphap, int oldslot) {
    int x = blockIdx.x * blockDim.x + threadIdx.x;
    if (x >= NODES) return;
    float gn = *gnp, alpha = *alphap;
    float* dtw_old = oldslot ? g_dtw1 : g_dtw0;
    float* dtw_new = oldslot ? g_dtw0 : g_dtw1;
    float vn = g_p2[x] + gn * (g_dtp1[x] - dtw_old[x]);
    float y2 = vn + gn * dtw_new[x];
    float up = fmaxf(fmaf(y2, y2, 4.f * gn * alpha), 1e-8f);
    g_p2[x] = 0.5f * (y2 - sqrtf(up));
    g_v[x] = vn;
    g_dtp1[x] = 0.f;
    dtw_old[x] = 0.f;   // becomes accumulator for DT(w_{t+2})
}

// Tiled edge pass: thread = column j (256 cols per CTA), CTA = 64-row tile.
// Column-endpoint DT sums accumulate in registers. Row-endpoint DT sums:
// each thread deposits packed (p1, wn) via one STS.64 into an 8-row smem
// chunk (double-buffered); after one barrier per chunk, warp w sums row w
// (8 strided LDS.64 + one butterfly per 2048 elems) and fires one global
// atomic per row. No per-element shuffles, no ballot, no smem atomics.
__global__ __launch_bounds__(256) void edge_kernel(
    const float* __restrict__ z,
    const float* __restrict__ wprev_base,
    float* __restrict__ wout_base,
    const float* __restrict__ gnp,
    const float* __restrict__ betap,
    int first, int nxtslot, long long UL)
{
    // 40 non-empty tiles: J=0 -> I=0..3, J=1 -> I=0..7, J=2 -> I=0..11, J=3 -> I=0..15
    int tid = blockIdx.x;
    int b = blockIdx.y;
    int I, J;
    if (tid < 4)       { J = 0; I = tid; }
    else if (tid < 12) { J = 1; I = tid - 4; }
    else if (tid < 24) { J = 2; I = tid - 12; }
    else               { J = 3; I = tid - 24; }
    int i0 = I * RT;
    int j  = J * 256 + (int)threadIdx.x;
    int lane = threadIdx.x & 31;
    int warp = threadIdx.x >> 5;

    float gn = *gnp, beta = *betap;
    float c1 = 1.f - 2.f * gn * beta;   // y1 = c1*w - gn*(v_i + v_j)
    float t2 = 2.f * gn;

    __shared__ __align__(16) float s_ngv[RT];
    __shared__ __align__(16) float s_ngp[RT];
    __shared__ float2 s_buf[2][CH * 256];   // 32 KB double-buffered chunk

    const float* vB = g_v  + b * MM;
    const float* pB = g_p2 + b * MM;
    for (int r = threadIdx.x; r < RT; r += 256) {
        int i = i0 + r;
        float vi = (i < MM) ? vB[i] : 0.f;
        float pi = (i < MM) ? pB[i] : 0.f;
        s_ngv[r] = -gn * vi;
        s_ngp[r] = -gn * pi;
    }
    __syncthreads();

    bool colv = (j < MM);
    float ngvj = colv ? -gn * vB[j] : 0.f;
    float ngpj = colv ? -gn * pB[j] : 0.f;
    float accP = 0.f, accW = 0.f;

    const float* zb = z + (size_t)b * LL;
    const float* wb = wprev_base + (size_t)b * UL;
    float*       ob = wout_base  + (size_t)b * UL;

    float* dtp1 = g_dtp1 + b * MM;
    float* dtw  = (nxtslot ? g_dtw1 : g_dtw0) + b * MM;

    // packed triu: rs(i) = i*(M-1) - i*(i-1)/2 ; e = rs(i) + j - i - 1
    int e = i0 * (MM - 1) - (i0 * (i0 - 1)) / 2 + j - i0 - 1;

    for (int c = 0; c < NCH; c++) {
        // row-constant node values for this chunk (2x LDS.128 per array)
        float4 a0 = *(const float4*)&s_ngv[c * CH];
        float4 a1 = *(const float4*)&s_ngv[c * CH + 4];
        float4 b0 = *(const float4*)&s_ngp[c * CH];
        float4 b1 = *(const float4*)&s_ngp[c * CH + 4];
        float rv[CH] = {a0.x, a0.y, a0.z, a0.w, a1.x, a1.y, a1.z, a1.w};
        float rp[CH] = {b0.x, b0.y, b0.z, b0.w, b1.x, b1.y, b1.z, b1.w};
        float2* buf = s_buf[c & 1];

        #pragma unroll
        for (int rr = 0; rr < CH; rr++) {
            int i = i0 + c * CH + rr;
            bool act = colv && (j > i);
            float zz = act ? zb[e] : 0.f;
            float w  = (act && !first) ? wb[e] : 0.f;
            float sv = rv[rr] + ngvj;
            float sp = rp[rr] + ngpj;
            float y1 = fmaf(c1, w, sv);
            float p1 = fmaxf(0.f, fmaf(-t2, zz, y1));
            float q1 = fmaf(c1, p1, sp);
            float wn = (w - y1) + q1;
            if (!act) { p1 = 0.f; wn = 0.f; }
            if (act) ob[e] = wn;
            accP += p1;
            accW += wn;
            buf[rr * 256 + threadIdx.x] = make_float2(p1, wn);
            e += (MM - 2 - i);
        }
        __syncthreads();

        // warp `warp` reduces row (c*CH + warp) of this chunk
        {
            int r = c * CH + warp;
            int i = i0 + r;
            const float2* rowp = buf + warp * 256;
            float sp = 0.f, sw = 0.f;
            #pragma unroll
            for (int k = 0; k < 8; k++) {
                float2 v = rowp[lane + 32 * k];
                sp += v.x; sw += v.y;
            }
            #pragma unroll
            for (int o = 16; o; o >>= 1) {
                sp += __shfl_xor_sync(0xFFFFFFFFu, sp, o);
                sw += __shfl_xor_sync(0xFFFFFFFFu, sw, o);
            }
            if (lane == 0 && i < MM - 1) {
                atomicAdd(&dtp1[i], sp);
                atomicAdd(&dtw[i],  sw);
            }
        }
    }

    if (colv && j > i0) {
        atomicAdd(&dtp1[j], accP);
        atomicAdd(&dtw[j],  accW);
    }
}

extern "C" void kernel_launch(void* const* d_in, const int* in_sizes, int n_in,
                              void* d_out, int out_size) {
    const float* z     = (const float*)d_in[0];
    const float* gn    = (const float*)d_in[1];
    const float* alpha = (const float*)d_in[2];
    const float* beta  = (const float*)d_in[3];
    float* out = (float*)d_out;
    int U = out_size / (BB * LL);
    if (U <= 0) U = 15;
    long long UL = (long long)U * LL;

    init_kernel<<<(NODES + 255) / 256, 256>>>(gn, alpha);

    int cur = 0;   // slot holding DT(w_t); initially DT(w_0)=0
    for (int t = 0; t < U; t++) {
        int nxt = cur ^ 1;
        const float* wprev = (t == 0) ? out : (out + (size_t)(t - 1) * LL);
        float*       wout  = out + (size_t)t * LL;
        edge_kernel<<<dim3(40, BB), 256>>>(z, wprev, wout, gn, beta,
                                           (t == 0) ? 1 : 0, nxt, UL);
        if (t + 1 < U)
            node_kernel<<<(NODES + 255) / 256, 256>>>(gn, alpha, cur);
        cur = nxt;
    }
}

// round 7
// speedup vs baseline: 2.5340x; 1.4808x over previous
#include <cuda_runtime.h>

#define MM 1000
#define BB 16
#define LL 499500            // MM*(MM-1)/2
#define NODES (BB * MM)
#define RT 32                // rows per CTA tile
#define CH 8                 // rows per smem chunk
#define NCH (RT / CH)        // 4 chunks
#define NITER 15

// Ping-pong node state (written redundantly+identically by every CTA of a pass)
__device__ float g_p2s[2][NODES];
__device__ float g_ds[2][NODES];       // d_t = v_t - p2_t
__device__ float g_dtwA[2][NODES];     // DT(w_t)
// Per-iteration DT(p1_t) accumulators, pre-zeroed by init each replay
__device__ float g_dtp1[NITER][NODES];

__global__ void init_kernel() {
    int x = blockIdx.x * blockDim.x + threadIdx.x;
    if (x < NITER * NODES) ((float*)g_dtp1)[x] = 0.f;
}

// Per-node update for pass t. Computes (v_t, p2_t); also stores DT(w_t), p2_t, d_t.
// Pure function of global state written by pass t-1 -> bitwise identical across CTAs.
template<bool FIRST>
__device__ __forceinline__ float2 node_upd(int t, int g, float gn, float alpha,
                                           float c1, float S) {
    float vt, p2, dtwc;
    if (FIRST) {
        vt = 0.f;
        dtwc = 0.f;
        p2 = -0.5f * sqrtf(fmaxf(4.f * gn * alpha, 1e-8f));
    } else {
        int po = (t - 1) & 1;
        float p2p  = g_p2s[po][g];
        float dp   = g_ds[po][g];
        float dtwp = g_dtwA[po][g];
        float dtp  = g_dtp1[t - 1][g];
        // DT(w_t) = (1-c1)DT(w_{t-1}) + c1 DT(p1_{t-1}) + gn[(M-2)d_{t-1} + S_{t-1}]
        dtwc = (1.f - c1) * dtwp + c1 * dtp + gn * ((float)(MM - 2) * dp + S);
        vt = p2p + gn * (dtp - dtwp);
        float y2 = vt + gn * dtwc;
        float up = fmaxf(fmaf(y2, y2, 4.f * gn * alpha), 1e-8f);
        p2 = 0.5f * (y2 - sqrtf(up));
    }
    int cc = t & 1;
    g_dtwA[cc][g] = dtwc;
    g_p2s[cc][g]  = p2;
    g_ds[cc][g]   = vt - p2;
    return make_float2(vt, p2);
}

// MODE: 2 = fully dense (all threads, all rows active)
//       1 = column-guard only (act = j < MM, row-invariant)
//       0 = diagonal (act = j < MM && j > i)
template<int MODE, bool FIRST>
__device__ __forceinline__ void edge_loop(
    int i0, int j, bool colv, int tx, int lane, int warp,
    const float* __restrict__ zb, const float* __restrict__ wb,
    float* __restrict__ ob, float* __restrict__ dtp1b,
    float c1, float t2,
    const float* s_ngv, const float* s_ngp,
    float ngvj, float ngpj, float (*s_buf)[CH * 256])
{
    float accP = 0.f;
    int e = i0 * (MM - 1) - (i0 * (i0 - 1)) / 2 + j - i0 - 1;
    int K = MM - 2 - i0;

    for (int c = 0; c < NCH; c++) {
        float4 a0 = *(const float4*)&s_ngv[c * CH];
        float4 a1 = *(const float4*)&s_ngv[c * CH + 4];
        float4 b0 = *(const float4*)&s_ngp[c * CH];
        float4 b1 = *(const float4*)&s_ngp[c * CH + 4];
        float rv[CH] = {a0.x, a0.y, a0.z, a0.w, a1.x, a1.y, a1.z, a1.w};
        float rp[CH] = {b0.x, b0.y, b0.z, b0.w, b1.x, b1.y, b1.z, b1.w};
        float* buf = s_buf[c & 1];

        #pragma unroll
        for (int rr = 0; rr < CH; rr++) {
            int row = c * CH + rr;
            int i = i0 + row;
            bool act;
            if (MODE == 2) act = true;
            else if (MODE == 1) act = colv;
            else act = colv && (j > i);
            float zz = act ? zb[e] : 0.f;
            float w  = (act && !FIRST) ? wb[e] : 0.f;
            float y1 = fmaf(c1, w, rv[rr] + ngvj);
            float p1 = fmaxf(0.f, fmaf(-t2, zz, y1));
            if (MODE != 2 && !act) p1 = 0.f;
            float q1 = fmaf(c1, p1, rp[rr] + ngpj);
            float wn = (w - y1) + q1;
            if (act) ob[e] = wn;
            accP += p1;
            buf[rr * 256 + tx] = p1;
            e += K - row;
        }
        __syncthreads();
        {   // warp `warp` reduces row c*CH+warp of this chunk
            int i = i0 + c * CH + warp;
            const float* rowp = s_buf[c & 1] + warp * 256;
            float s = 0.f;
            #pragma unroll
            for (int k = 0; k < 8; k++) s += rowp[lane + 32 * k];
            #pragma unroll
            for (int o = 16; o; o >>= 1) s += __shfl_xor_sync(0xFFFFFFFFu, s, o);
            if (lane == 0 && i < MM - 1) atomicAdd(&dtp1b[i], s);
        }
    }
    if (colv && j > i0) atomicAdd(&dtp1b[j], accP);
}

template<bool FIRST>
__global__ void __launch_bounds__(256, 5) edge_kernel(
    const float* __restrict__ z,
    const float* __restrict__ wprev,
    float* __restrict__ wout,
    const float* __restrict__ gnp,
    const float* __restrict__ alphap,
    const float* __restrict__ betap,
    int t, long long UL)
{
    int tid = blockIdx.x;
    int b = blockIdx.y;
    int tx = threadIdx.x, lane = tx & 31, warp = tx >> 5;

    // 80 tiles (RT=32): J=0:I0-7 | J=1:I0-15 | J=2:I0-23 | J=3:I0-31
    int I, J, mode;
    if (tid < 8)       { J = 0; I = tid;      mode = 0; }
    else if (tid < 24) { J = 1; I = tid - 8;  mode = (I < 8)  ? 2 : 0; }
    else if (tid < 48) { J = 2; I = tid - 24; mode = (I < 16) ? 2 : 0; }
    else               { J = 3; I = tid - 48; mode = (I < 24) ? 1 : 0; }
    int i0 = I * RT;
    int j  = J * 256 + tx;
    bool colv = (j < MM);

    float gn = *gnp, alpha = *alphap, beta = *betap;
    float c1 = 1.f - 2.f * gn * beta;
    float t2 = 2.f * gn;

    __shared__ __align__(16) float s_ngv[RT];
    __shared__ __align__(16) float s_ngp[RT];
    __shared__ float s_buf[2][CH * 256];
    __shared__ float s_red[8];
    __shared__ float s_S;

    // ---- S_{t-1} = sum over this batch of d_{t-1} (deterministic, CTA-independent) ----
    float S = 0.f;
    if (!FIRST) {
        const float* dsb = g_ds[(t - 1) & 1] + b * MM;
        float part = 0.f;
        #pragma unroll
        for (int k = 0; k < 4; k++) { int x = tx + 256 * k; if (x < MM) part += dsb[x]; }
        #pragma unroll
        for (int o = 16; o; o >>= 1) part += __shfl_xor_sync(0xFFFFFFFFu, part, o);
        if (lane == 0) s_red[warp] = part;
        __syncthreads();
        if (warp == 0) {
            float v = (lane < 8) ? s_red[lane] : 0.f;
            #pragma unroll
            for (int o = 4; o; o >>= 1) v += __shfl_xor_sync(0xFFFFFFFFu, v, o);
            if (lane == 0) s_S = v;
        }
        __syncthreads();
        S = s_S;
    }

    // ---- fused node update (redundant per CTA; identical values) ----
    float ngvj = 0.f, ngpj = 0.f;
    if (colv) {
        float2 vp = node_upd<FIRST>(t, b * MM + j, gn, alpha, c1, S);
        ngvj = -gn * vp.x; ngpj = -gn * vp.y;
    }
    if (tx < RT) {
        int i = i0 + tx;
        if (i < MM) {
            float2 vp = node_upd<FIRST>(t, b * MM + i, gn, alpha, c1, S);
            s_ngv[tx] = -gn * vp.x; s_ngp[tx] = -gn * vp.y;
        } else { s_ngv[tx] = 0.f; s_ngp[tx] = 0.f; }
    }
    __syncthreads();

    const float* zb = z + (size_t)b * LL;
    const float* wb = wprev + (size_t)b * UL;
    float*       ob = wout + (size_t)b * UL;
    float* dtp1b = g_dtp1[t] + b * MM;

    if (mode == 2)
        edge_loop<2, FIRST>(i0, j, colv, tx, lane, warp, zb, wb, ob, dtp1b,
                            c1, t2, s_ngv, s_ngp, ngvj, ngpj, s_buf);
    else if (mode == 1)
        edge_loop<1, FIRST>(i0, j, colv, tx, lane, warp, zb, wb, ob, dtp1b,
                            c1, t2, s_ngv, s_ngp, ngvj, ngpj, s_buf);
    else
        edge_loop<0, FIRST>(i0, j, colv, tx, lane, warp, zb, wb, ob, dtp1b,
                            c1, t2, s_ngv, s_ngp, ngvj, ngpj, s_buf);
}

extern "C" void kernel_launch(void* const* d_in, const int* in_sizes, int n_in,
                              void* d_out, int out_size) {
    const float* z     = (const float*)d_in[0];
    const float* gn    = (const float*)d_in[1];
    const float* alpha = (const float*)d_in[2];
    const float* beta  = (const float*)d_in[3];
    float* out = (float*)d_out;
    int U = out_size / (BB * LL);
    if (U <= 0 || U > NITER) U = NITER;
    long long UL = (long long)U * LL;

    init_kernel<<<(NITER * NODES + 255) / 256, 256>>>();

    for (int t = 0; t < U; t++) {
        const float* wprev = (t == 0) ? out : (out + (size_t)(t - 1) * LL);
        float*       wout  = out + (size_t)t * LL;
        if (t == 0)
            edge_kernel<true><<<dim3(80, BB), 256>>>(z, wprev, wout, gn, alpha, beta, 0, UL);
        else
            edge_kernel<false><<<dim3(80, BB), 256>>>(z, wprev, wout, gn, alpha, beta, t, UL);
    }
}

// round 11
// speedup vs baseline: 2.8887x; 1.1400x over previous
#include <cuda_runtime.h>

#define MM 1000
#define BB 16
#define LL 499500            // MM*(MM-1)/2
#define NODES (BB * MM)
#define RT 32                // rows per CTA tile
#define CH 8                 // rows per smem chunk
#define NCH (RT / CH)        // 4 chunks
#define NITER 15

// Ping-pong node state (written redundantly+identically by every CTA of a pass)
__device__ float g_p2s[2][NODES];
__device__ float g_ds[2][NODES];       // d_t = v_t - p2_t
__device__ float g_dtwA[2][NODES];     // DT(w_t)
// Per-iteration DT(p1_t) accumulators, pre-zeroed by init each replay
__device__ float g_dtp1[NITER][NODES];

__device__ __forceinline__ unsigned long long pol_evict_last() {
    unsigned long long p;
    asm("createpolicy.fractional.L2::evict_last.b64 %0, 1.0;" : "=l"(p));
    return p;
}
__device__ __forceinline__ unsigned long long pol_evict_first() {
    unsigned long long p;
    asm("createpolicy.fractional.L2::evict_first.b64 %0, 1.0;" : "=l"(p));
    return p;
}
__device__ __forceinline__ float ldg_pol(const float* p, unsigned long long pol) {
    float v;
    asm volatile("ld.global.nc.L2::cache_hint.f32 %0, [%1], %2;"
                 : "=f"(v) : "l"(p), "l"(pol));
    return v;
}

__global__ void init_kernel() {
    int x = blockIdx.x * blockDim.x + threadIdx.x;
    if (x < NITER * NODES) ((float*)g_dtp1)[x] = 0.f;
}

// Per-node update for pass t (redundant per CTA, bitwise identical).
template<bool FIRST>
__device__ __forceinline__ float2 node_upd(int t, int g, float gn, float alpha,
                                           float c1, float S) {
    float vt, p2, dtwc;
    if (FIRST) {
        vt = 0.f;
        dtwc = 0.f;
        p2 = -0.5f * sqrtf(fmaxf(4.f * gn * alpha, 1e-8f));
    } else {
        int po = (t - 1) & 1;
        float p2p  = g_p2s[po][g];
        float dp   = g_ds[po][g];
        float dtwp = g_dtwA[po][g];
        float dtp  = g_dtp1[t - 1][g];
        dtwc = (1.f - c1) * dtwp + c1 * dtp + gn * ((float)(MM - 2) * dp + S);
        vt = p2p + gn * (dtp - dtwp);
        float y2 = vt + gn * dtwc;
        float up = fmaxf(fmaf(y2, y2, 4.f * gn * alpha), 1e-8f);
        p2 = 0.5f * (y2 - sqrtf(up));
    }
    int cc = t & 1;
    g_dtwA[cc][g] = dtwc;
    g_p2s[cc][g]  = p2;
    g_ds[cc][g]   = vt - p2;
    return make_float2(vt, p2);
}

// MODE: 2 dense | 1 column-guard only | 0 diagonal
template<int MODE, bool FIRST>
__device__ __forceinline__ void edge_loop(
    int i0, int j, bool colv, int tx, int lane, int warp,
    const float* __restrict__ zb, const float* __restrict__ wb,
    float* __restrict__ ob, float* __restrict__ dtp1b,
    float c1, float t2,
    const float* s_ngv, const float* s_ngp,
    float ngvj, float ngpj, float2 (*s_buf)[(CH / 2) * 256],
    unsigned long long polZ, unsigned long long polW)
{
    float accP = 0.f;
    int e = i0 * (MM - 1) - (i0 * (i0 - 1)) / 2 + j - i0 - 1;
    int K = MM - 2 - i0;

    for (int c = 0; c < NCH; c++) {
        float4 a0 = *(const float4*)&s_ngv[c * CH];
        float4 a1 = *(const float4*)&s_ngv[c * CH + 4];
        float4 b0 = *(const float4*)&s_ngp[c * CH];
        float4 b1 = *(const float4*)&s_ngp[c * CH + 4];
        float rv[CH] = {a0.x, a0.y, a0.z, a0.w, a1.x, a1.y, a1.z, a1.w};
        float rp[CH] = {b0.x, b0.y, b0.z, b0.w, b1.x, b1.y, b1.z, b1.w};
        float2* buf = s_buf[c & 1];

        // front-batched loads for the whole chunk (max MLP)
        float zv[CH], wv[CH];
        {
            int e2 = e;
            #pragma unroll
            for (int rr = 0; rr < CH; rr++) {
                int row = c * CH + rr;
                int i = i0 + row;
                bool act;
                if (MODE == 2) act = true;
                else if (MODE == 1) act = colv;
                else act = colv && (j > i);
                zv[rr] = act ? ldg_pol(zb + e2, polZ) : 0.f;
                wv[rr] = (act && !FIRST) ? ldg_pol(wb + e2, polW) : 0.f;
                e2 += K - row;
            }
        }

        float2 dep;
        #pragma unroll
        for (int rr = 0; rr < CH; rr++) {
            int row = c * CH + rr;
            int i = i0 + row;
            bool act;
            if (MODE == 2) act = true;
            else if (MODE == 1) act = colv;
            else act = colv && (j > i);
            float y1 = fmaf(c1, wv[rr], rv[rr] + ngvj);
            float p1 = fmaxf(0.f, fmaf(-t2, zv[rr], y1));
            if (MODE != 2 && !act) p1 = 0.f;
            float q1 = fmaf(c1, p1, rp[rr] + ngpj);
            float wn = (wv[rr] - y1) + q1;
            if (act) ob[e] = wn;
            accP += p1;
            if (rr & 1) { dep.y = p1; buf[(rr >> 1) * 256 + tx] = dep; }
            else dep.x = p1;
            e += K - row;
        }
        __syncthreads();

        // warps 0-3 reduce row-pairs of this chunk
        if (warp < CH / 2) {
            const float2* rowp = buf + warp * 256;
            float sx = 0.f, sy = 0.f;
            #pragma unroll
            for (int k = 0; k < 8; k++) {
                float2 v = rowp[lane + 32 * k];
                sx += v.x; sy += v.y;
            }
            #pragma unroll
            for (int o = 16; o; o >>= 1) {
                sx += __shfl_xor_sync(0xFFFFFFFFu, sx, o);
                sy += __shfl_xor_sync(0xFFFFFFFFu, sy, o);
            }
            if (lane == 0) {
                int ie = i0 + c * CH + 2 * warp;
                if (ie < MM - 1)     atomicAdd(&dtp1b[ie], sx);
                if (ie + 1 < MM - 1) atomicAdd(&dtp1b[ie + 1], sy);
            }
        }
    }
    if (colv && j > i0) atomicAdd(&dtp1b[j], accP);
}

template<bool FIRST>
__global__ void __launch_bounds__(256, 4) edge_kernel(
    const float* __restrict__ z,
    const float* __restrict__ wprev,
    float* __restrict__ wout,
    const float* __restrict__ gnp,
    const float* __restrict__ alphap,
    const float* __restrict__ betap,
    int t, long long UL)
{
    int tid = blockIdx.x;
    int b = blockIdx.y;
    int tx = threadIdx.x, lane = tx & 31, warp = tx >> 5;

    // dense tiles first (heaviest work starts earliest), then mode1, then diag
    int I, J, mode;
    if (tid < 24) {            // dense: J=1 I0-7, J=2 I0-15
        mode = 2;
        if (tid < 8) { J = 1; I = tid; } else { J = 2; I = tid - 8; }
    } else if (tid < 48) {     // column-guard: J=3 I0-23
        mode = 1; J = 3; I = tid - 24;
    } else {                   // diagonal: I = k, J = k/8
        mode = 0; int k = tid - 48; J = k >> 3; I = k;
    }
    int i0 = I * RT;
    int j  = J * 256 + tx;
    bool colv = (j < MM);

    float gn = *gnp, alpha = *alphap, beta = *betap;
    float c1 = 1.f - 2.f * gn * beta;
    float t2 = 2.f * gn;

    unsigned long long polZ = pol_evict_last();
    unsigned long long polW = pol_evict_first();

    __shared__ __align__(16) float s_ngv[RT];
    __shared__ __align__(16) float s_ngp[RT];
    __shared__ float2 s_buf[2][(CH / 2) * 256];
    __shared__ float s_red[8];
    __shared__ float s_S;

    // S_{t-1} = sum_b d_{t-1}
    float S = 0.f;
    if (!FIRST) {
        const float* dsb = g_ds[(t - 1) & 1] + b * MM;
        float part = 0.f;
        #pragma unroll
        for (int k = 0; k < 4; k++) { int x = tx + 256 * k; if (x < MM) part += dsb[x]; }
        #pragma unroll
        for (int o = 16; o; o >>= 1) part += __shfl_xor_sync(0xFFFFFFFFu, part, o);
        if (lane == 0) s_red[warp] = part;
        __syncthreads();
        if (warp == 0) {
            float v = (lane < 8) ? s_red[lane] : 0.f;
            #pragma unroll
            for (int o = 4; o; o >>= 1) v += __shfl_xor_sync(0xFFFFFFFFu, v, o);
            if (lane == 0) s_S = v;
        }
        __syncthreads();
        S = s_S;
    }

    // fused node update (redundant per CTA; identical values)
    float ngvj = 0.f, ngpj = 0.f;
    if (colv) {
        float2 vp = node_upd<FIRST>(t, b * MM + j, gn, alpha, c1, S);
        ngvj = -gn * vp.x; ngpj = -gn * vp.y;
    }
    if (tx < RT) {
        int i = i0 + tx;
        if (i < MM) {
            float2 vp = node_upd<FIRST>(t, b * MM + i, gn, alpha, c1, S);
            s_ngv[tx] = -gn * vp.x; s_ngp[tx] = -gn * vp.y;
        } else { s_ngv[tx] = 0.f; s_ngp[tx] = 0.f; }
    }
    __syncthreads();

    const float* zb = z + (size_t)b * LL;
    const float* wb = wprev + (size_t)b * UL;
    float*       ob = wout + (size_t)b * UL;
    float* dtp1b = g_dtp1[t] + b * MM;

    if (mode == 2)
        edge_loop<2, FIRST>(i0, j, colv, tx, lane, warp, zb, wb, ob, dtp1b,
                            c1, t2, s_ngv, s_ngp, ngvj, ngpj, s_buf, polZ, polW);
    else if (mode == 1)
        edge_loop<1, FIRST>(i0, j, colv, tx, lane, warp, zb, wb, ob, dtp1b,
                            c1, t2, s_ngv, s_ngp, ngvj, ngpj, s_buf, polZ, polW);
    else
        edge_loop<0, FIRST>(i0, j, colv, tx, lane, warp, zb, wb, ob, dtp1b,
                            c1, t2, s_ngv, s_ngp, ngvj, ngpj, s_buf, polZ, polW);
}

extern "C" void kernel_launch(void* const* d_in, const int* in_sizes, int n_in,
                              void* d_out, int out_size) {
    const float* z     = (const float*)d_in[0];
    const float* gn    = (const float*)d_in[1];
    const float* alpha = (const float*)d_in[2];
    const float* beta  = (const float*)d_in[3];
    float* out = (float*)d_out;
    int U = out_size / (BB * LL);
    if (U <= 0 || U > NITER) U = NITER;
    long long UL = (long long)U * LL;

    init_kernel<<<(NITER * NODES + 255) / 256, 256>>>();

    for (int t = 0; t < U; t++) {
        const float* wprev = (t == 0) ? out : (out + (size_t)(t - 1) * LL);
        float*       wout  = out + (size_t)t * LL;
        if (t == 0)
            edge_kernel<true><<<dim3(80, BB), 256>>>(z, wprev, wout, gn, alpha, beta, 0, UL);
        else
            edge_kernel<false><<<dim3(80, BB), 256>>>(z, wprev, wout, gn, alpha, beta, t, UL);
    }
}